// round 11
// baseline (speedup 1.0000x reference)
#include <cuda_runtime.h>
#include <cuda_fp16.h>
#include <cstdint>
#include <cstddef>

// NeRD pixel decoder, fully fused per image row — fp16 mma.sync m16n8k16,
// ldmatrix.x4 fragment loads, 3-stage cp.async staging pipeline.
// 512 threads / 16 warps (4 per SMSP) for latency hiding; warp tile 64m x 32n.
// Weights pre-scaled by 2^8 (exact); epilogue multiplies acc by 2^-8.
//
//   Layer 0: implicit 5x5 conv GEMM [128 x 3200] @ [3200 x 256], 100 K=32 slabs
//   Layers 1,2: [128 x 256] @ [256 x 256], 8 K=32 slabs each
//   Head: [128 x 256] @ [256 x 3] scalar
// One CTA = one (batch, image-row).
//
// R9 bug fixed here: stage_A must cover 528 float4 chunks; with 512 threads
// that needs TWO passes (tid, tid+512<528), not a single `if (tid < 528)`.
//
// ldmatrix bank checks (8-row wavefronts, 16B/row):
//   A/B slabs stride 40 halves = 20 words: banks {20r..20r+3 mod 32} distinct
//   smH stride 264 halves = 132 words (≡4 mod 32): banks {4r..4r+3} distinct

#define FC   128
#define HID  256
#define OUTC 3
#define IMH  128
#define IMW  128
#define OMEGA 30.0f
#define THREADS 512
#define WSCALE 256.0f
#define INV_WSCALE 0.00390625f

#define SMH_H 264                   // smH stride (halves)
#define SMA_H 40                    // A slab stride
#define SMB_H 40                    // B slab stride
#define SMH_HALF (128 * SMH_H)      // 33792
#define SMA_HALF (132 * SMA_H)      // 5280
#define SMB_HALF (256 * SMB_H)      // 10240
#define OFF_B(st) (SMH_HALF + (st) * SMB_HALF)
#define SMEM_BYTES ((SMH_HALF + 3 * SMB_HALF) * 2)   // 129024 B

// ---- persistent scratch: pre-tiled fp16 slabs in exact staging order ----
__device__ __half g_xiA[2 * 4 * 132 * 4224];     // [(b*4+cb)*132+hp][(j*132+wa)*8+e]
__device__ __half g_W0s[25 * 4 * 8192];          // [tap][cb][(j*256+n)*8+e] *2^8
__device__ __half g_W1s[8 * 8192];               // [kb][(j*256+n)*8+e]      *2^8
__device__ __half g_W2s[8 * 8192];

__device__ __forceinline__ void mma16(float* c, const unsigned* a, unsigned b0, unsigned b1) {
    asm("mma.sync.aligned.m16n8k16.row.col.f32.f16.f16.f32 "
        "{%0,%1,%2,%3}, {%4,%5,%6,%7}, {%8,%9}, {%0,%1,%2,%3};"
        : "+f"(c[0]), "+f"(c[1]), "+f"(c[2]), "+f"(c[3])
        : "r"(a[0]), "r"(a[1]), "r"(a[2]), "r"(a[3]), "r"(b0), "r"(b1));
}

__device__ __forceinline__ void ldsm4(unsigned& r0, unsigned& r1, unsigned& r2,
                                      unsigned& r3, unsigned addr) {
    asm volatile("ldmatrix.sync.aligned.m8n8.x4.shared.b16 {%0,%1,%2,%3}, [%4];"
                 : "=r"(r0), "=r"(r1), "=r"(r2), "=r"(r3) : "r"(addr));
}

__device__ __forceinline__ void cpa16(unsigned dst, const void* src) {
    asm volatile("cp.async.ca.shared.global [%0], [%1], 16;" :: "r"(dst), "l"(src));
}
#define CP_COMMIT asm volatile("cp.async.commit_group;" ::: "memory")
#define CP_WAIT(n) asm volatile("cp.async.wait_group %0;" :: "n"(n) : "memory")

// ================= prep kernels =================
// Direct scatter, one block per (b, cb, hp): grid 1056.
extern "C" __global__ void prep_xi_kernel(const float* __restrict__ xi) {
    const int bi = blockIdx.x;
    const int hp = bi % 132;
    const int t  = bi / 132;
    const int cb = t & 3, b = t >> 2;
    const int h  = hp - 2;
    const bool hok = (unsigned)h < IMH;
    __half* dst = g_xiA + (((size_t)(b * 4 + cb)) * 132 + hp) * 4224;
    for (int r = threadIdx.x; r < 4224; r += blockDim.x) {
        const int e = r & 7, wj = r >> 3;
        const int wa = wj % 132, j = wj / 132;
        const int c = cb * 32 + j * 8 + e;
        const int w = wa - 2;
        float v = 0.f;
        if (hok && (unsigned)w < IMW)
            v = xi[(((size_t)b * FC + c) * IMH + h) * IMW + w];
        dst[r] = __float2half_rn(v);
    }
}

extern "C" __global__ void prep_w_kernel(const float* __restrict__ W0,
                                         const float* __restrict__ W1,
                                         const float* __restrict__ W2) {
    int idx = blockIdx.x * blockDim.x + threadIdx.x;
    const int NW0 = 25 * 4 * 8192;             // slab 8192 = 2^13: shifts valid
    if (idx < NW0) {
        const int e = idx & 7, n = (idx >> 3) & 255, j = (idx >> 11) & 3;
        const int cb = (idx >> 13) & 3, tap = idx >> 15;
        const int c = cb * 32 + j * 8 + e;
        g_W0s[idx] = __float2half_rn(W0[((size_t)c * 25 + tap) * HID + n] * WSCALE);
    } else {
        int r = idx - NW0;
        if (r >= 2 * 65536) return;
        const int which = r >> 16; r &= 65535;
        const int e = r & 7, n = (r >> 3) & 255, j = (r >> 11) & 3, kb = r >> 13;
        const int k = kb * 32 + j * 8 + e;
        const float v = (which ? W2 : W1)[(size_t)k * HID + n] * WSCALE;
        if (which) g_W2s[r] = __float2half_rn(v);
        else       g_W1s[r] = __float2half_rn(v);
    }
}

// ================= main fused kernel =================
extern "C" __global__ void __launch_bounds__(THREADS, 1)
nerd_fused_kernel(const float* __restrict__ W0f, const float* __restrict__ b0,
                  const float* __restrict__ b1, const float* __restrict__ b2,
                  const float* __restrict__ W3, const float* __restrict__ b3,
                  float* __restrict__ out)
{
    extern __shared__ __half smem[];
    __half* smH = smem;                              // [128][264]
    const unsigned sbase = (unsigned)__cvta_generic_to_shared(smem);

    const int tid  = threadIdx.x;
    const int lane = tid & 31, warp = tid >> 5;      // 16 warps
    const int wm = warp >> 3, wn = warp & 7;         // 2 x 8 grid, warp tile 64x32
    const int lr = lane >> 2, lc = lane & 3;
    const int l15 = lane & 15, lhi = lane >> 4;      // ldmatrix lane split
    const int bx = blockIdx.x, bimg = bx >> 7, hrow = bx & 127;

    float acc[64];                                   // [mt4][nt4][4]
#pragma unroll
    for (int i = 0; i < 64; ++i) acc[i] = 0.f;

    // ---- staging helpers (cp.async); 512 threads ----
    const int bn   = tid & 255;                      // B chunk: n index
    const int bhalf = tid >> 8;                      // B chunk: k half
    auto stage_B0 = [&](int s) {                     // layer-0 B slab for iter s
        const int g = s / 5, pw = s - g * 5;
        const int ph = g >> 2, cb = g & 3;
        const __half* src = g_W0s + ((size_t)(ph * 5 + pw) * 4 + cb) * 8192;
        const unsigned dst = sbase + OFF_B(s % 3) * 2;
#pragma unroll
        for (int l = 0; l < 2; ++l) {
            const int jj = bhalf * 2 + l;            // 0..3
            cpa16(dst + (bn * SMB_H + jj * 8) * 2, src + ((size_t)jj * 256 + bn) * 8);
        }
    };
    auto stage_BL = [&](const __half* Ws, int kb) {  // layers 1/2
        const __half* src = Ws + (size_t)kb * 8192;
        const unsigned dst = sbase + OFF_B(kb % 3) * 2;
#pragma unroll
        for (int l = 0; l < 2; ++l) {
            const int jj = bhalf * 2 + l;
            cpa16(dst + (bn * SMB_H + jj * 8) * 2, src + ((size_t)jj * 256 + bn) * 8);
        }
    };
    auto stage_A = [&](int g) {                      // xi slab for group g = ph*4+cb
        const int ph = g >> 2, cb = g & 3;
        const __half* src = g_xiA + (((size_t)(bimg * 4 + cb)) * 132 + hrow + ph) * 4224;
        const unsigned dst = sbase + ((g & 1) * SMA_HALF) * 2;
#pragma unroll
        for (int l = 0; l < 2; ++l) {                // 528 chunks / 512 threads
            const int idx = tid + l * 512;
            if (idx < 528)
                cpa16(dst + ((idx % 132) * SMA_H + (idx / 132) * 8) * 2,
                      src + (size_t)idx * 8);
        }
    };

    // ---- prologue: groups 0 (A0+B0) and 1 (B1) ----
    stage_A(0); stage_B0(0); CP_COMMIT;
    stage_B0(1); CP_COMMIT;

    // ================= Layer 0: 100 K=32 slabs, 3-stage pipeline =============
    for (int s = 0; s < 100; ++s) {
        const int g = s / 5, pw = s - g * 5;
        CP_WAIT(1);                                  // group s complete
        __syncthreads();                             // all warps done with iter s-1
        if (s + 2 < 100) stage_B0(s + 2);
        if (pw == 3 && g + 1 < 20) stage_A(g + 1);
        CP_COMMIT;

        const unsigned aB = sbase + ((g & 1) * SMA_HALF) * 2;
        const unsigned bB = sbase + OFF_B(s % 3) * 2;
#pragma unroll
        for (int kk = 0; kk < 2; ++kk) {
            const int col = kk * 16 + lhi * 8;
            unsigned a[4][4];
#pragma unroll
            for (int mt = 0; mt < 4; ++mt) {
                const int row = wm * 64 + mt * 16 + l15 + pw;   // halo shift
                ldsm4(a[mt][0], a[mt][1], a[mt][2], a[mt][3],
                      aB + (row * SMA_H + col) * 2);
            }
#pragma unroll
            for (int np = 0; np < 2; ++np) {                    // nt pairs
                unsigned b0a, b0b, b1a, b1b;
                const int nrow = wn * 32 + np * 16 + l15;
                ldsm4(b0a, b0b, b1a, b1b, bB + (nrow * SMB_H + col) * 2);
#pragma unroll
                for (int mt = 0; mt < 4; ++mt) {
                    mma16(&acc[(mt * 4 + 2 * np) * 4],     a[mt], b0a, b1a);
                    mma16(&acc[(mt * 4 + 2 * np + 1) * 4], a[mt], b0b, b1b);
                }
            }
        }
    }
    CP_WAIT(0);
    __syncthreads();

    // ---- layer-0 epilogue: acc/256 + coords + b0, sin -> smH (fp16) ----
    {
        const float gy = -1.f + 2.f * (float)hrow * (1.f / 127.f);
#pragma unroll
        for (int mt = 0; mt < 4; ++mt)
#pragma unroll
            for (int nt = 0; nt < 4; ++nt)
#pragma unroll
                for (int hf = 0; hf < 2; ++hf) {
                    const int m = wm * 64 + mt * 16 + lr + hf * 8;
                    const int n0 = wn * 32 + nt * 8 + lc * 2;
                    const float gx = -1.f + 2.f * (float)m * (1.f / 127.f);
                    const float z0 = acc[(mt * 4 + nt) * 4 + hf * 2 + 0] * INV_WSCALE
                                   + gx * W0f[3200 * HID + n0] + gy * W0f[3201 * HID + n0] + b0[n0];
                    const float z1 = acc[(mt * 4 + nt) * 4 + hf * 2 + 1] * INV_WSCALE
                                   + gx * W0f[3200 * HID + n0 + 1] + gy * W0f[3201 * HID + n0 + 1] + b0[n0 + 1];
                    *(__half2*)(smH + m * SMH_H + n0) =
                        __floats2half2_rn(__sinf(OMEGA * z0), __sinf(OMEGA * z1));
                }
    }
    __syncthreads();

    // ================= Layers 1 and 2 (3-stage pipeline over 8 k-slabs) ======
    for (int L = 0; L < 2; ++L) {
        const __half* Ws = L ? g_W2s : g_W1s;
        const float* bl = L ? b2 : b1;
#pragma unroll
        for (int i = 0; i < 64; ++i) acc[i] = 0.f;

        stage_BL(Ws, 0); CP_COMMIT;
        stage_BL(Ws, 1); CP_COMMIT;

        for (int kb = 0; kb < 8; ++kb) {
            CP_WAIT(1);
            __syncthreads();
            if (kb + 2 < 8) stage_BL(Ws, kb + 2);
            CP_COMMIT;

            const unsigned bB = sbase + OFF_B(kb % 3) * 2;
#pragma unroll
            for (int kk = 0; kk < 2; ++kk) {
                const int colH = kb * 32 + kk * 16 + lhi * 8;   // k in smH
                const int colB = kk * 16 + lhi * 8;             // k in B slab
                unsigned a[4][4];
#pragma unroll
                for (int mt = 0; mt < 4; ++mt) {
                    const int row = wm * 64 + mt * 16 + l15;
                    ldsm4(a[mt][0], a[mt][1], a[mt][2], a[mt][3],
                          sbase + (row * SMH_H + colH) * 2);
                }
#pragma unroll
                for (int np = 0; np < 2; ++np) {
                    unsigned b0a, b0b, b1a, b1b;
                    const int nrow = wn * 32 + np * 16 + l15;
                    ldsm4(b0a, b0b, b1a, b1b, bB + (nrow * SMB_H + colB) * 2);
#pragma unroll
                    for (int mt = 0; mt < 4; ++mt) {
                        mma16(&acc[(mt * 4 + 2 * np) * 4],     a[mt], b0a, b1a);
                        mma16(&acc[(mt * 4 + 2 * np + 1) * 4], a[mt], b0b, b1b);
                    }
                }
            }
        }
        CP_WAIT(0);
        __syncthreads();

        // epilogue: acc/256 + bl, sin -> smH
#pragma unroll
        for (int mt = 0; mt < 4; ++mt)
#pragma unroll
            for (int nt = 0; nt < 4; ++nt)
#pragma unroll
                for (int hf = 0; hf < 2; ++hf) {
                    const int m = wm * 64 + mt * 16 + lr + hf * 8;
                    const int n0 = wn * 32 + nt * 8 + lc * 2;
                    const float z0 = acc[(mt * 4 + nt) * 4 + hf * 2 + 0] * INV_WSCALE + bl[n0];
                    const float z1 = acc[(mt * 4 + nt) * 4 + hf * 2 + 1] * INV_WSCALE + bl[n0 + 1];
                    *(__half2*)(smH + m * SMH_H + n0) =
                        __floats2half2_rn(__sinf(OMEGA * z0), __sinf(OMEGA * z1));
                }
        __syncthreads();
    }

    // ================= Head: [128 x 256] @ [256 x 3] + b3 =================
    if (tid < IMW * OUTC) {
        const int p = tid & 127, o = tid >> 7;
        float sum = b3[o];
#pragma unroll 4
        for (int k = 0; k < HID; k += 2) {
            const float2 f = __half22float2(*(const __half2*)(smH + p * SMH_H + k));
            sum += f.x * W3[k * OUTC + o] + f.y * W3[(k + 1) * OUTC + o];
        }
        out[(((size_t)bimg * OUTC + o) * IMH + hrow) * IMW + p] = sum;
    }
}

extern "C" void kernel_launch(void* const* d_in, const int* in_sizes, int n_in,
                              void* d_out, int out_size)
{
    const float* xi = (const float*)d_in[0];
    const float* W0 = (const float*)d_in[1];
    const float* b0 = (const float*)d_in[2];
    const float* W1 = (const float*)d_in[3];
    const float* b1 = (const float*)d_in[4];
    const float* W2 = (const float*)d_in[5];
    const float* b2 = (const float*)d_in[6];
    const float* W3 = (const float*)d_in[7];
    const float* b3 = (const float*)d_in[8];
    float* out = (float*)d_out;

    cudaFuncSetAttribute(nerd_fused_kernel,
                         cudaFuncAttributeMaxDynamicSharedMemorySize, SMEM_BYTES);

    prep_xi_kernel<<<2 * 4 * 132, 128>>>(xi);
    const int n_w = 25 * 4 * 8192 + 2 * 65536;
    prep_w_kernel<<<(n_w + 255) / 256, 256>>>(W0, W1, W2);

    nerd_fused_kernel<<<256, THREADS, SMEM_BYTES>>>(W0, b0, b1, b2, W3, b3, out);
}

// round 12
// speedup vs baseline: 1.0707x; 1.0707x over previous
#include <cuda_runtime.h>
#include <cuda_fp16.h>
#include <cstdint>
#include <cstddef>

// NeRD pixel decoder, fully fused per image row — fp16 mma.sync m16n8k16,
// ldmatrix.x4, cp.async, K=64 slabs (half the barriers of the K=32 version).
// 256 threads / 8 warps (measured-best), warp tile 64m x 64n, acc fp32.
// Weights pre-scaled by 2^8 (exact); epilogue multiplies acc by 2^-8.
//
//   Layer 0: [128 x 3200] @ [3200 x 256] as 50 K=64 slabs (25 taps x 2 ch-halves)
//   Layers 1,2: [128 x 256] @ [256 x 256] as 4 K=64 slabs each
//   Head: [128 x 256] @ [256 x 3] scalar
// One CTA = one (batch, image-row).
//
// Bank checks (ldsm 8-row wavefronts, 16B rows):
//   A/B slabs stride 72 halves = 36 words (≡4 mod 32): banks {4r..4r+3} distinct
//   smH stride 264 halves = 132 words (≡4 mod 32): same pattern, distinct

#define FC   128
#define HID  256
#define OUTC 3
#define IMH  128
#define IMW  128
#define OMEGA 30.0f
#define THREADS 256
#define WSCALE 256.0f
#define INV_WSCALE 0.00390625f

#define SMH_H 264                   // smH stride (halves)
#define SMA_H 72                    // A slab stride (64 + 8 pad)
#define SMB_H 72                    // B slab stride
#define SMH_HALF (128 * SMH_H)      // 33792
#define SMA_HALF (132 * SMA_H)      // 9504  (two buffers alias into smH)
#define SMB_HALF (256 * SMB_H)      // 18432
#define OFF_B(st) (SMH_HALF + (st) * SMB_HALF)
#define SMEM_BYTES ((SMH_HALF + 3 * SMB_HALF) * 2)   // 178176 B

// ---- persistent scratch: pre-tiled fp16, contiguous per slab ----
// g_xiA[((b*2+ch)*132+hp)*132+wa][kc]   (c = ch*64 + kc), zero-padded
__device__ __half g_xiA[2 * 2 * 132 * 132 * 64];   // 8.9 MB
// g_W0s[((tap*2)+ch)*256+n][kc]         (c = ch*64 + kc), *2^8
__device__ __half g_W0s[25 * 2 * 256 * 64];
// g_W1s[(kb*256+n)][kc]                 (k = kb*64 + kc), *2^8
__device__ __half g_W1s[4 * 256 * 64];
__device__ __half g_W2s[4 * 256 * 64];

__device__ __forceinline__ void mma16(float* c, const unsigned* a, unsigned b0, unsigned b1) {
    asm("mma.sync.aligned.m16n8k16.row.col.f32.f16.f16.f32 "
        "{%0,%1,%2,%3}, {%4,%5,%6,%7}, {%8,%9}, {%0,%1,%2,%3};"
        : "+f"(c[0]), "+f"(c[1]), "+f"(c[2]), "+f"(c[3])
        : "r"(a[0]), "r"(a[1]), "r"(a[2]), "r"(a[3]), "r"(b0), "r"(b1));
}

__device__ __forceinline__ void ldsm4(unsigned& r0, unsigned& r1, unsigned& r2,
                                      unsigned& r3, unsigned addr) {
    asm volatile("ldmatrix.sync.aligned.m8n8.x4.shared.b16 {%0,%1,%2,%3}, [%4];"
                 : "=r"(r0), "=r"(r1), "=r"(r2), "=r"(r3) : "r"(addr));
}

__device__ __forceinline__ void cpa16(unsigned dst, const void* src) {
    asm volatile("cp.async.ca.shared.global [%0], [%1], 16;" :: "r"(dst), "l"(src));
}
#define CP_COMMIT asm volatile("cp.async.commit_group;" ::: "memory")
#define CP_WAIT(n) asm volatile("cp.async.wait_group %0;" :: "n"(n) : "memory")

// ================= prep kernels =================
// One block per (b, ch, hp): grid 528. Writes contiguous, reads gathered.
extern "C" __global__ void prep_xi_kernel(const float* __restrict__ xi) {
    const int bi = blockIdx.x;
    const int hp = bi % 132;
    const int t  = bi / 132;
    const int ch = t & 1, b = t >> 1;
    const int h  = hp - 2;
    const bool hok = (unsigned)h < IMH;
    __half* dst = g_xiA + ((size_t)bi) * (132 * 64);
    for (int r = threadIdx.x; r < 132 * 64; r += blockDim.x) {
        const int kc = r & 63, wa = r >> 6;
        const int c = ch * 64 + kc;
        const int w = wa - 2;
        float v = 0.f;
        if (hok && (unsigned)w < IMW)
            v = xi[(((size_t)b * FC + c) * IMH + h) * IMW + w];
        dst[r] = __float2half_rn(v);
    }
}

extern "C" __global__ void prep_w_kernel(const float* __restrict__ W0,
                                         const float* __restrict__ W1,
                                         const float* __restrict__ W2) {
    int idx = blockIdx.x * blockDim.x + threadIdx.x;
    const int NW0 = 25 * 2 * 256 * 64;         // 819200
    if (idx < NW0) {
        const int kc = idx & 63, n = (idx >> 6) & 255;
        const int ch = (idx >> 14) & 1, tap = idx >> 15;
        const int c = ch * 64 + kc;
        g_W0s[idx] = __float2half_rn(W0[((size_t)c * 25 + tap) * HID + n] * WSCALE);
    } else {
        int r = idx - NW0;
        if (r >= 2 * 65536) return;
        const int which = r >> 16; r &= 65535;
        const int kc = r & 63, n = (r >> 6) & 255, kb = r >> 14;
        const int k = kb * 64 + kc;
        const float v = (which ? W2 : W1)[(size_t)k * HID + n] * WSCALE;
        if (which) g_W2s[r] = __float2half_rn(v);
        else       g_W1s[r] = __float2half_rn(v);
    }
}

// ================= main fused kernel =================
extern "C" __global__ void __launch_bounds__(THREADS, 1)
nerd_fused_kernel(const float* __restrict__ W0f, const float* __restrict__ b0,
                  const float* __restrict__ b1, const float* __restrict__ b2,
                  const float* __restrict__ W3, const float* __restrict__ b3,
                  float* __restrict__ out)
{
    extern __shared__ __half smem[];
    __half* smH = smem;                              // [128][264]
    const unsigned sbase = (unsigned)__cvta_generic_to_shared(smem);

    const int tid  = threadIdx.x;
    const int lane = tid & 31, warp = tid >> 5;      // 8 warps
    const int wm = warp >> 2, wn = warp & 3;         // 2 x 4 grid, tile 64x64
    const int lr = lane >> 2, lc = lane & 3;
    const int l15 = lane & 15, lhi = lane >> 4;
    const int bx = blockIdx.x, bimg = bx >> 7, hrow = bx & 127;

    float acc[128];                                  // [mt4][nt8][4]
#pragma unroll
    for (int i = 0; i < 128; ++i) acc[i] = 0.f;

    // ---- staging helpers (cp.async); 256 threads ----
    // B slab: 256 rows x 64 halves = 2048 float4 chunks, 8 passes.
    auto stage_B0 = [&](int s) {                     // s = 0..49: g=s/5, pw=s%5
        const int g = s / 5, pw = s - g * 5;
        const int ph = g >> 1, ch = g & 1;
        const int tap = ph * 5 + pw;
        const __half* src = g_W0s + ((size_t)(tap * 2 + ch)) * 16384;
        const unsigned dst = sbase + OFF_B(s % 3) * 2;
#pragma unroll
        for (int l = 0; l < 8; ++l) {
            const int idx = tid + l * 256;
            const int n = idx >> 3, j = idx & 7;
            cpa16(dst + (n * SMB_H + j * 8) * 2, src + (size_t)idx * 8);
        }
    };
    auto stage_BL = [&](const __half* Ws, int kb) {
        const __half* src = Ws + (size_t)kb * 16384;
        const unsigned dst = sbase + OFF_B(kb % 3) * 2;
#pragma unroll
        for (int l = 0; l < 8; ++l) {
            const int idx = tid + l * 256;
            const int n = idx >> 3, j = idx & 7;
            cpa16(dst + (n * SMB_H + j * 8) * 2, src + (size_t)idx * 8);
        }
    };
    // A slab: 132 rows x 64 halves = 1056 float4 chunks, 5 guarded passes.
    auto stage_A = [&](int g) {                      // g = ph*2 + ch
        const int ph = g >> 1, ch = g & 1;
        const __half* src = g_xiA +
            ((size_t)((bimg * 2 + ch) * 132 + hrow + ph)) * (132 * 64);
        const unsigned dst = sbase + ((g & 1) * SMA_HALF) * 2;
#pragma unroll
        for (int l = 0; l < 5; ++l) {
            const int idx = tid + l * 256;
            if (idx < 1056) {
                const int wa = idx >> 3, j = idx & 7;
                cpa16(dst + (wa * SMA_H + j * 8) * 2, src + (size_t)idx * 8);
            }
        }
    };

    // ---- prologue ----
    stage_A(0); stage_B0(0); CP_COMMIT;
    stage_B0(1); CP_COMMIT;

    // ================= Layer 0: 50 K=64 slabs, 3-stage B pipeline ============
    for (int s = 0; s < 50; ++s) {
        const int g = s / 5, pw = s - g * 5;
        CP_WAIT(1);                                  // slab s resident
        __syncthreads();
        if (s + 2 < 50) stage_B0(s + 2);
        if (pw == 3 && g + 1 < 10) stage_A(g + 1);   // used from s+2 on
        CP_COMMIT;

        const unsigned aB = sbase + ((g & 1) * SMA_HALF) * 2;
        const unsigned bB = sbase + OFF_B(s % 3) * 2;
#pragma unroll
        for (int kk = 0; kk < 4; ++kk) {
            const int col = kk * 16 + lhi * 8;
            unsigned a[4][4];
#pragma unroll
            for (int mt = 0; mt < 4; ++mt) {
                const int row = wm * 64 + mt * 16 + l15 + pw;   // halo shift
                ldsm4(a[mt][0], a[mt][1], a[mt][2], a[mt][3],
                      aB + (row * SMA_H + col) * 2);
            }
#pragma unroll
            for (int np = 0; np < 4; ++np) {
                unsigned b0a, b0b, b1a, b1b;
                const int nrow = wn * 64 + np * 16 + l15;
                ldsm4(b0a, b0b, b1a, b1b, bB + (nrow * SMB_H + col) * 2);
#pragma unroll
                for (int mt = 0; mt < 4; ++mt) {
                    mma16(&acc[(mt * 8 + 2 * np) * 4],     a[mt], b0a, b1a);
                    mma16(&acc[(mt * 8 + 2 * np + 1) * 4], a[mt], b0b, b1b);
                }
            }
        }
    }
    CP_WAIT(0);
    __syncthreads();

    // ---- layer-0 epilogue: acc/256 + coords + b0, sin -> smH (fp16) ----
    {
        const float gy = -1.f + 2.f * (float)hrow * (1.f / 127.f);
#pragma unroll
        for (int mt = 0; mt < 4; ++mt)
#pragma unroll
            for (int nt = 0; nt < 8; ++nt)
#pragma unroll
                for (int hf = 0; hf < 2; ++hf) {
                    const int m = wm * 64 + mt * 16 + lr + hf * 8;
                    const int n0 = wn * 64 + nt * 8 + lc * 2;
                    const float gx = -1.f + 2.f * (float)m * (1.f / 127.f);
                    const float z0 = acc[(mt * 8 + nt) * 4 + hf * 2 + 0] * INV_WSCALE
                                   + gx * W0f[3200 * HID + n0] + gy * W0f[3201 * HID + n0] + b0[n0];
                    const float z1 = acc[(mt * 8 + nt) * 4 + hf * 2 + 1] * INV_WSCALE
                                   + gx * W0f[3200 * HID + n0 + 1] + gy * W0f[3201 * HID + n0 + 1] + b0[n0 + 1];
                    *(__half2*)(smH + m * SMH_H + n0) =
                        __floats2half2_rn(__sinf(OMEGA * z0), __sinf(OMEGA * z1));
                }
    }
    __syncthreads();

    // ================= Layers 1 and 2: 4 K=64 slabs each =====================
    for (int L = 0; L < 2; ++L) {
        const __half* Ws = L ? g_W2s : g_W1s;
        const float* bl = L ? b2 : b1;
#pragma unroll
        for (int i = 0; i < 128; ++i) acc[i] = 0.f;

        stage_BL(Ws, 0); CP_COMMIT;
        stage_BL(Ws, 1); CP_COMMIT;

        for (int kb = 0; kb < 4; ++kb) {
            CP_WAIT(1);
            __syncthreads();
            if (kb + 2 < 4) stage_BL(Ws, kb + 2);
            CP_COMMIT;

            const unsigned bB = sbase + OFF_B(kb % 3) * 2;
#pragma unroll
            for (int kk = 0; kk < 4; ++kk) {
                const int colH = kb * 64 + kk * 16 + lhi * 8;   // k in smH
                const int colB = kk * 16 + lhi * 8;             // k in B slab
                unsigned a[4][4];
#pragma unroll
                for (int mt = 0; mt < 4; ++mt) {
                    const int row = wm * 64 + mt * 16 + l15;
                    ldsm4(a[mt][0], a[mt][1], a[mt][2], a[mt][3],
                          sbase + (row * SMH_H + colH) * 2);
                }
#pragma unroll
                for (int np = 0; np < 4; ++np) {
                    unsigned b0a, b0b, b1a, b1b;
                    const int nrow = wn * 64 + np * 16 + l15;
                    ldsm4(b0a, b0b, b1a, b1b, bB + (nrow * SMB_H + colB) * 2);
#pragma unroll
                    for (int mt = 0; mt < 4; ++mt) {
                        mma16(&acc[(mt * 8 + 2 * np) * 4],     a[mt], b0a, b1a);
                        mma16(&acc[(mt * 8 + 2 * np + 1) * 4], a[mt], b0b, b1b);
                    }
                }
            }
        }
        CP_WAIT(0);
        __syncthreads();

        // epilogue: acc/256 + bl, sin -> smH
#pragma unroll
        for (int mt = 0; mt < 4; ++mt)
#pragma unroll
            for (int nt = 0; nt < 8; ++nt)
#pragma unroll
                for (int hf = 0; hf < 2; ++hf) {
                    const int m = wm * 64 + mt * 16 + lr + hf * 8;
                    const int n0 = wn * 64 + nt * 8 + lc * 2;
                    const float z0 = acc[(mt * 8 + nt) * 4 + hf * 2 + 0] * INV_WSCALE + bl[n0];
                    const float z1 = acc[(mt * 8 + nt) * 4 + hf * 2 + 1] * INV_WSCALE + bl[n0 + 1];
                    *(__half2*)(smH + m * SMH_H + n0) =
                        __floats2half2_rn(__sinf(OMEGA * z0), __sinf(OMEGA * z1));
                }
        __syncthreads();
    }

    // ================= Head: [128 x 256] @ [256 x 3] + b3 =================
    for (int idx = tid; idx < IMW * OUTC; idx += THREADS) {
        const int p = idx & 127, o = idx >> 7;
        float sum = b3[o];
#pragma unroll 4
        for (int k = 0; k < HID; k += 2) {
            const float2 f = __half22float2(*(const __half2*)(smH + p * SMH_H + k));
            sum += f.x * W3[k * OUTC + o] + f.y * W3[(k + 1) * OUTC + o];
        }
        out[(((size_t)bimg * OUTC + o) * IMH + hrow) * IMW + p] = sum;
    }
}

extern "C" void kernel_launch(void* const* d_in, const int* in_sizes, int n_in,
                              void* d_out, int out_size)
{
    const float* xi = (const float*)d_in[0];
    const float* W0 = (const float*)d_in[1];
    const float* b0 = (const float*)d_in[2];
    const float* W1 = (const float*)d_in[3];
    const float* b1 = (const float*)d_in[4];
    const float* W2 = (const float*)d_in[5];
    const float* b2 = (const float*)d_in[6];
    const float* W3 = (const float*)d_in[7];
    const float* b3 = (const float*)d_in[8];
    float* out = (float*)d_out;

    cudaFuncSetAttribute(nerd_fused_kernel,
                         cudaFuncAttributeMaxDynamicSharedMemorySize, SMEM_BYTES);

    prep_xi_kernel<<<2 * 2 * 132, 256>>>(xi);
    const int n_w = 25 * 2 * 256 * 64 + 2 * 65536;
    prep_w_kernel<<<(n_w + 255) / 256, 256>>>(W0, W1, W2);

    nerd_fused_kernel<<<256, THREADS, SMEM_BYTES>>>(W0, b0, b1, b2, W3, b3, out);
}

// round 13
// speedup vs baseline: 1.1458x; 1.0702x over previous
#include <cuda_runtime.h>
#include <cuda_fp16.h>
#include <cstdint>
#include <cstddef>

// NeRD pixel decoder, fully fused per image row — fp16 mma.sync m16n8k16,
// ldmatrix.x4, cp.async, K=64 slabs, explicit 2-deep fragment pipeline
// (LDSM for kk+1 overlaps MMAs of kk). Single fused prep kernel
// (2 launches per call -> ncu -s 5 -c 1 lands on the main kernel).
// Weights pre-scaled by 2^8 (exact); epilogue multiplies acc by 2^-8.
//
//   Layer 0: [128 x 3200] @ [3200 x 256] as 50 K=64 slabs (25 taps x 2 ch)
//   Layers 1,2: [128 x 256] @ [256 x 256] as 4 K=64 slabs each
//   Head: [128 x 256] @ [256 x 3] scalar
// One CTA = one (batch, image-row). 8 warps, warp tile 64x64, acc fp32.
//
// Bank checks (ldsm 8-row wavefronts, 16B rows):
//   A/B slabs stride 72 halves = 36 words (≡4 mod 32): banks {4r..4r+3} distinct
//   smH stride 264 halves = 132 words (≡4 mod 32): same, distinct

#define FC   128
#define HID  256
#define OUTC 3
#define IMH  128
#define IMW  128
#define OMEGA 30.0f
#define THREADS 256
#define WSCALE 256.0f
#define INV_WSCALE 0.00390625f

#define SMH_H 264
#define SMA_H 72
#define SMB_H 72
#define SMH_HALF (128 * SMH_H)      // 33792
#define SMA_HALF (132 * SMA_H)      // 9504 (x2 alias into smH)
#define SMB_HALF (256 * SMB_H)      // 18432
#define OFF_B(st) (SMH_HALF + (st) * SMB_HALF)
#define SMEM_BYTES ((SMH_HALF + 3 * SMB_HALF) * 2)   // 178176 B

// ---- persistent scratch: pre-tiled fp16, contiguous per slab ----
__device__ __half g_xiA[2 * 2 * 132 * 132 * 64];   // [((b*2+ch)*132+hp)][wa*64+kc]
__device__ __half g_W0s[25 * 2 * 256 * 64];        // [(tap*2+ch)*256+n][kc] *2^8
__device__ __half g_W1s[4 * 256 * 64];             // [(kb*256+n)][kc]      *2^8
__device__ __half g_W2s[4 * 256 * 64];

__device__ __forceinline__ void mma16(float* c, const unsigned* a, unsigned b0, unsigned b1) {
    asm("mma.sync.aligned.m16n8k16.row.col.f32.f16.f16.f32 "
        "{%0,%1,%2,%3}, {%4,%5,%6,%7}, {%8,%9}, {%0,%1,%2,%3};"
        : "+f"(c[0]), "+f"(c[1]), "+f"(c[2]), "+f"(c[3])
        : "r"(a[0]), "r"(a[1]), "r"(a[2]), "r"(a[3]), "r"(b0), "r"(b1));
}

__device__ __forceinline__ void ldsm4(unsigned& r0, unsigned& r1, unsigned& r2,
                                      unsigned& r3, unsigned addr) {
    asm volatile("ldmatrix.sync.aligned.m8n8.x4.shared.b16 {%0,%1,%2,%3}, [%4];"
                 : "=r"(r0), "=r"(r1), "=r"(r2), "=r"(r3) : "r"(addr));
}

__device__ __forceinline__ void cpa16(unsigned dst, const void* src) {
    asm volatile("cp.async.ca.shared.global [%0], [%1], 16;" :: "r"(dst), "l"(src));
}
#define CP_COMMIT asm volatile("cp.async.commit_group;" ::: "memory")
#define CP_WAIT(n) asm volatile("cp.async.wait_group %0;" :: "n"(n) : "memory")

// ================= fused prep kernel =================
// blocks [0, 528): xi transpose, one per (b, ch, hp); coalesced reads via smT.
// blocks [528, 992): weights, 2048 elems each (950272 total = 464 blocks).
#define XI_BLOCKS 528
extern "C" __global__ void prep_kernel(const float* __restrict__ xi,
                                       const float* __restrict__ W0,
                                       const float* __restrict__ W1,
                                       const float* __restrict__ W2) {
    const int tid = threadIdx.x;
    if (blockIdx.x < XI_BLOCKS) {
        __shared__ __half smT[64][134];            // [kc][wp], stride 67 words
        const int bi = blockIdx.x;
        const int hp = bi % 132;
        const int t  = bi / 132;
        const int ch = t & 1, b = t >> 1;
        const int h  = hp - 2;
        const bool hok = (unsigned)h < IMH;
        // zero padded columns
        if (tid < 64) {
            smT[tid][0] = __half(0); smT[tid][1] = __half(0);
            smT[tid][130] = __half(0); smT[tid][131] = __half(0);
        }
        // coalesced load: 2 channel-rows per pass
        const int w = tid & 127, cl0 = tid >> 7;
        for (int cc = 0; cc < 64; cc += 2) {
            const int cl = cc + cl0;
            float v = 0.f;
            if (hok)
                v = xi[(((size_t)b * FC + ch * 64 + cl) * IMH + h) * IMW + w];
            smT[cl][w + 2] = __float2half_rn(v);
        }
        __syncthreads();
        // contiguous write: dst[r], r = wa*64 + kc (half2 per thread)
        __half2* dst2 = (__half2*)(g_xiA + ((size_t)bi) * (132 * 64));
        for (int r2 = tid; r2 < 132 * 32; r2 += THREADS) {
            const int kc2 = r2 & 31, wa = r2 >> 5;
            dst2[r2] = __halves2half2(smT[2 * kc2][wa], smT[2 * kc2 + 1][wa]);
        }
    } else {
        const int base = (blockIdx.x - XI_BLOCKS) * 2048;
        const int NW0 = 25 * 2 * 256 * 64;         // 819200
#pragma unroll
        for (int l = 0; l < 8; ++l) {
            const int idx = base + l * 256 + tid;
            if (idx < NW0) {
                const int kc = idx & 63, n = (idx >> 6) & 255;
                const int ch = (idx >> 14) & 1, tap = idx >> 15;
                const int c = ch * 64 + kc;
                g_W0s[idx] = __float2half_rn(W0[((size_t)c * 25 + tap) * HID + n] * WSCALE);
            } else {
                int r = idx - NW0;
                if (r < 2 * 65536) {
                    const int which = r >> 16; r &= 65535;
                    const int kc = r & 63, n = (r >> 6) & 255, kb = r >> 14;
                    const int k = kb * 64 + kc;
                    const float v = (which ? W2 : W1)[(size_t)k * HID + n] * WSCALE;
                    if (which) g_W2s[r] = __float2half_rn(v);
                    else       g_W1s[r] = __float2half_rn(v);
                }
            }
        }
    }
}

// ================= main fused kernel =================
extern "C" __global__ void __launch_bounds__(THREADS, 1)
nerd_fused_kernel(const float* __restrict__ W0f, const float* __restrict__ b0,
                  const float* __restrict__ b1, const float* __restrict__ b2,
                  const float* __restrict__ W3, const float* __restrict__ b3,
                  float* __restrict__ out)
{
    extern __shared__ __half smem[];
    __half* smH = smem;                              // [128][264]
    const unsigned sbase = (unsigned)__cvta_generic_to_shared(smem);

    const int tid  = threadIdx.x;
    const int lane = tid & 31, warp = tid >> 5;      // 8 warps
    const int wm = warp >> 2, wn = warp & 3;         // 2 x 4 grid, tile 64x64
    const int lr = lane >> 2, lc = lane & 3;
    const int l15 = lane & 15, lhi = lane >> 4;
    const int bx = blockIdx.x, bimg = bx >> 7, hrow = bx & 127;

    float acc[128];                                  // [mt4][nt8][4]
#pragma unroll
    for (int i = 0; i < 128; ++i) acc[i] = 0.f;

    // ---- staging helpers (cp.async); 256 threads ----
    auto stage_B0 = [&](int s) {
        const int g = s / 5, pw = s - g * 5;
        const int ph = g >> 1, ch = g & 1;
        const int tap = ph * 5 + pw;
        const __half* src = g_W0s + ((size_t)(tap * 2 + ch)) * 16384;
        const unsigned dst = sbase + OFF_B(s % 3) * 2;
#pragma unroll
        for (int l = 0; l < 8; ++l) {
            const int idx = tid + l * 256;
            const int n = idx >> 3, j = idx & 7;
            cpa16(dst + (n * SMB_H + j * 8) * 2, src + (size_t)idx * 8);
        }
    };
    auto stage_BL = [&](const __half* Ws, int kb) {
        const __half* src = Ws + (size_t)kb * 16384;
        const unsigned dst = sbase + OFF_B(kb % 3) * 2;
#pragma unroll
        for (int l = 0; l < 8; ++l) {
            const int idx = tid + l * 256;
            const int n = idx >> 3, j = idx & 7;
            cpa16(dst + (n * SMB_H + j * 8) * 2, src + (size_t)idx * 8);
        }
    };
    auto stage_A = [&](int g) {                      // g = ph*2 + ch
        const int ph = g >> 1, ch = g & 1;
        const __half* src = g_xiA +
            ((size_t)((bimg * 2 + ch) * 132 + hrow + ph)) * (132 * 64);
        const unsigned dst = sbase + ((g & 1) * SMA_HALF) * 2;
#pragma unroll
        for (int l = 0; l < 5; ++l) {
            const int idx = tid + l * 256;
            if (idx < 1056) {
                const int wa = idx >> 3, j = idx & 7;
                cpa16(dst + (wa * SMA_H + j * 8) * 2, src + (size_t)idx * 8);
            }
        }
    };

    // ---- prologue ----
    stage_A(0); stage_B0(0); CP_COMMIT;
    stage_B0(1); CP_COMMIT;

    // fragment load for layer 0 (explicit buffers for kk pipelining)
    unsigned af[2][4][4], bf[2][4][4];

    // ================= Layer 0: 50 K=64 slabs ================================
    for (int s = 0; s < 50; ++s) {
        const int g = s / 5, pw = s - g * 5;
        CP_WAIT(1);                                  // slab s resident
        __syncthreads();
        if (s + 2 < 50) stage_B0(s + 2);
        if (pw == 3 && g + 1 < 10) stage_A(g + 1);
        CP_COMMIT;

        const unsigned aB = sbase + ((g & 1) * SMA_HALF) * 2;
        const unsigned bB = sbase + OFF_B(s % 3) * 2;

#define LD_FRAGS0(kk_, buf_) do {                                              \
        const int col_ = (kk_) * 16 + lhi * 8;                                 \
        _Pragma("unroll") for (int mt = 0; mt < 4; ++mt) {                     \
            const int row_ = wm * 64 + mt * 16 + l15 + pw;                     \
            ldsm4(af[buf_][mt][0], af[buf_][mt][1], af[buf_][mt][2],           \
                  af[buf_][mt][3], aB + (row_ * SMA_H + col_) * 2);            \
        }                                                                      \
        _Pragma("unroll") for (int np = 0; np < 4; ++np) {                     \
            const int nrow_ = wn * 64 + np * 16 + l15;                         \
            ldsm4(bf[buf_][np][0], bf[buf_][np][1], bf[buf_][np][2],           \
                  bf[buf_][np][3], bB + (nrow_ * SMB_H + col_) * 2);           \
        } } while (0)

        LD_FRAGS0(0, 0);
#pragma unroll
        for (int kk = 0; kk < 4; ++kk) {
            if (kk < 3) {
                if ((kk & 1) == 0) LD_FRAGS0(kk + 1, 1);
                else               LD_FRAGS0(kk + 1, 0);
            }
            const int cur = kk & 1;
#pragma unroll
            for (int np = 0; np < 4; ++np)
#pragma unroll
                for (int mt = 0; mt < 4; ++mt) {
                    mma16(&acc[(mt * 8 + 2 * np) * 4],     af[cur][mt], bf[cur][np][0], bf[cur][np][2]);
                    mma16(&acc[(mt * 8 + 2 * np + 1) * 4], af[cur][mt], bf[cur][np][1], bf[cur][np][3]);
                }
        }
#undef LD_FRAGS0
    }
    CP_WAIT(0);
    __syncthreads();

    // ---- layer-0 epilogue: acc/256 + coords + b0, sin -> smH (fp16) ----
    {
        const float gy = -1.f + 2.f * (float)hrow * (1.f / 127.f);
#pragma unroll
        for (int mt = 0; mt < 4; ++mt)
#pragma unroll
            for (int nt = 0; nt < 8; ++nt)
#pragma unroll
                for (int hf = 0; hf < 2; ++hf) {
                    const int m = wm * 64 + mt * 16 + lr + hf * 8;
                    const int n0 = wn * 64 + nt * 8 + lc * 2;
                    const float gx = -1.f + 2.f * (float)m * (1.f / 127.f);
                    const float z0 = acc[(mt * 8 + nt) * 4 + hf * 2 + 0] * INV_WSCALE
                                   + gx * W0f[3200 * HID + n0] + gy * W0f[3201 * HID + n0] + b0[n0];
                    const float z1 = acc[(mt * 8 + nt) * 4 + hf * 2 + 1] * INV_WSCALE
                                   + gx * W0f[3200 * HID + n0 + 1] + gy * W0f[3201 * HID + n0 + 1] + b0[n0 + 1];
                    *(__half2*)(smH + m * SMH_H + n0) =
                        __floats2half2_rn(__sinf(OMEGA * z0), __sinf(OMEGA * z1));
                }
    }
    __syncthreads();

    // ================= Layers 1 and 2: 4 K=64 slabs each =====================
    for (int L = 0; L < 2; ++L) {
        const __half* Ws = L ? g_W2s : g_W1s;
        const float* bl = L ? b2 : b1;
#pragma unroll
        for (int i = 0; i < 128; ++i) acc[i] = 0.f;

        stage_BL(Ws, 0); CP_COMMIT;
        stage_BL(Ws, 1); CP_COMMIT;

        for (int kb = 0; kb < 4; ++kb) {
            CP_WAIT(1);
            __syncthreads();
            if (kb + 2 < 4) stage_BL(Ws, kb + 2);
            CP_COMMIT;

            const unsigned bB = sbase + OFF_B(kb % 3) * 2;

#define LD_FRAGSL(kk_, buf_) do {                                              \
        const int colH_ = kb * 64 + (kk_) * 16 + lhi * 8;                      \
        const int colB_ = (kk_) * 16 + lhi * 8;                                \
        _Pragma("unroll") for (int mt = 0; mt < 4; ++mt) {                     \
            const int row_ = wm * 64 + mt * 16 + l15;                          \
            ldsm4(af[buf_][mt][0], af[buf_][mt][1], af[buf_][mt][2],           \
                  af[buf_][mt][3], sbase + (row_ * SMH_H + colH_) * 2);        \
        }                                                                      \
        _Pragma("unroll") for (int np = 0; np < 4; ++np) {                     \
            const int nrow_ = wn * 64 + np * 16 + l15;                         \
            ldsm4(bf[buf_][np][0], bf[buf_][np][1], bf[buf_][np][2],           \
                  bf[buf_][np][3], bB + (nrow_ * SMB_H + colB_) * 2);          \
        } } while (0)

            LD_FRAGSL(0, 0);
#pragma unroll
            for (int kk = 0; kk < 4; ++kk) {
                if (kk < 3) {
                    if ((kk & 1) == 0) LD_FRAGSL(kk + 1, 1);
                    else               LD_FRAGSL(kk + 1, 0);
                }
                const int cur = kk & 1;
#pragma unroll
                for (int np = 0; np < 4; ++np)
#pragma unroll
                    for (int mt = 0; mt < 4; ++mt) {
                        mma16(&acc[(mt * 8 + 2 * np) * 4],     af[cur][mt], bf[cur][np][0], bf[cur][np][2]);
                        mma16(&acc[(mt * 8 + 2 * np + 1) * 4], af[cur][mt], bf[cur][np][1], bf[cur][np][3]);
                    }
            }
#undef LD_FRAGSL
        }
        CP_WAIT(0);
        __syncthreads();

        // epilogue: acc/256 + bl, sin -> smH
#pragma unroll
        for (int mt = 0; mt < 4; ++mt)
#pragma unroll
            for (int nt = 0; nt < 8; ++nt)
#pragma unroll
                for (int hf = 0; hf < 2; ++hf) {
                    const int m = wm * 64 + mt * 16 + lr + hf * 8;
                    const int n0 = wn * 64 + nt * 8 + lc * 2;
                    const float z0 = acc[(mt * 8 + nt) * 4 + hf * 2 + 0] * INV_WSCALE + bl[n0];
                    const float z1 = acc[(mt * 8 + nt) * 4 + hf * 2 + 1] * INV_WSCALE + bl[n0 + 1];
                    *(__half2*)(smH + m * SMH_H + n0) =
                        __floats2half2_rn(__sinf(OMEGA * z0), __sinf(OMEGA * z1));
                }
        __syncthreads();
    }

    // ================= Head: [128 x 256] @ [256 x 3] + b3 =================
    for (int idx = tid; idx < IMW * OUTC; idx += THREADS) {
        const int p = idx & 127, o = idx >> 7;
        float sum = b3[o];
#pragma unroll 4
        for (int k = 0; k < HID; k += 2) {
            const float2 f = __half22float2(*(const __half2*)(smH + p * SMH_H + k));
            sum += f.x * W3[k * OUTC + o] + f.y * W3[(k + 1) * OUTC + o];
        }
        out[(((size_t)bimg * OUTC + o) * IMH + hrow) * IMW + p] = sum;
    }
}

extern "C" void kernel_launch(void* const* d_in, const int* in_sizes, int n_in,
                              void* d_out, int out_size)
{
    const float* xi = (const float*)d_in[0];
    const float* W0 = (const float*)d_in[1];
    const float* b0 = (const float*)d_in[2];
    const float* W1 = (const float*)d_in[3];
    const float* b1 = (const float*)d_in[4];
    const float* W2 = (const float*)d_in[5];
    const float* b2 = (const float*)d_in[6];
    const float* W3 = (const float*)d_in[7];
    const float* b3 = (const float*)d_in[8];
    float* out = (float*)d_out;

    cudaFuncSetAttribute(nerd_fused_kernel,
                         cudaFuncAttributeMaxDynamicSharedMemorySize, SMEM_BYTES);

    prep_kernel<<<XI_BLOCKS + 464, THREADS>>>(xi, W0, W1, W2);
    nerd_fused_kernel<<<256, THREADS, SMEM_BYTES>>>(W0, b0, b1, b2, W3, b3, out);
}